// round 9
// baseline (speedup 1.0000x reference)
#include <cuda_runtime.h>
#include <cuda_bf16.h>
#include <mma.h>
#include <cstdint>

using namespace nvcuda;

#define N_NODES   100000
#define N_EDGES   1600000
#define D_FEAT    128
#define HIDDEN    128
#define N_CLASSES 10
#define NUM_GRAPHS 64
#define N_PAD     100096   // 782 * 128

typedef __nv_bfloat16 bf16;
typedef __nv_bfloat162 bf162;

// ---------------- scratch (no allocs allowed) ----------------
// activation row = 256 bf16: [128 hi | 128 lo]  (512 bytes)
__device__ bf16 g_xhl [(size_t)N_PAD * 256];
__device__ bf16 g_ahl [(size_t)N_PAD * 256];
__device__ bf16 g_h0hl[(size_t)N_PAD * 256];
__device__ bf16 g_h1hl[(size_t)N_PAD * 256];
// weight row (per layer, per out-neuron n): 512 bf16: [256 hi (Wl|Wr) | 256 lo]
__device__ bf16 g_whl[3 * 128 * 512];
__device__ float g_pooled[NUM_GRAPHS * HIDDEN];
__device__ int   g_deg [N_NODES];
__device__ int   g_off [N_NODES + 1];
__device__ int   g_cur [N_NODES];
__device__ int   g_srcs[N_EDGES];

// ---------------- helpers ----------------
__device__ __forceinline__ uint32_t smem_u32(const void* p) {
    uint32_t a;
    asm("{ .reg .u64 t; cvta.to.shared.u64 t, %1; cvt.u32.u64 %0, t; }" : "=r"(a) : "l"(p));
    return a;
}
__device__ __forceinline__ void cp16(uint32_t dst, const void* src) {
    asm volatile("cp.async.cg.shared.global [%0], [%1], 16;" :: "r"(dst), "l"(src));
}
#define CP_COMMIT() asm volatile("cp.async.commit_group;" ::: "memory")
#define CP_WAIT1()  asm volatile("cp.async.wait_group 1;" ::: "memory")
#define CP_WAIT0()  asm volatile("cp.async.wait_group 0;" ::: "memory")

// split float4 -> hi/lo uint2 (4 bf16 each)
__device__ __forceinline__ void split4(float4 v, uint2& hi, uint2& lo) {
    bf162 h0, h1, l0, l1;
    h0.x = __float2bfloat16(v.x); h0.y = __float2bfloat16(v.y);
    h1.x = __float2bfloat16(v.z); h1.y = __float2bfloat16(v.w);
    l0.x = __float2bfloat16(v.x - __bfloat162float(h0.x));
    l0.y = __float2bfloat16(v.y - __bfloat162float(h0.y));
    l1.x = __float2bfloat16(v.z - __bfloat162float(h1.x));
    l1.y = __float2bfloat16(v.w - __bfloat162float(h1.y));
    hi.x = *reinterpret_cast<uint32_t*>(&h0); hi.y = *reinterpret_cast<uint32_t*>(&h1);
    lo.x = *reinterpret_cast<uint32_t*>(&l0); lo.y = *reinterpret_cast<uint32_t*>(&l1);
}
// unpack uint4 (8 bf16) into 8 floats added to acc
__device__ __forceinline__ void add8(float* acc, uint4 v) {
    float2 f;
    f = __bfloat1622float2(*reinterpret_cast<bf162*>(&v.x)); acc[0] += f.x; acc[1] += f.y;
    f = __bfloat1622float2(*reinterpret_cast<bf162*>(&v.y)); acc[2] += f.x; acc[3] += f.y;
    f = __bfloat1622float2(*reinterpret_cast<bf162*>(&v.z)); acc[4] += f.x; acc[5] += f.y;
    f = __bfloat1622float2(*reinterpret_cast<bf162*>(&v.w)); acc[6] += f.x; acc[7] += f.y;
}

// ---------------- conversions ----------------
__global__ void __launch_bounds__(256) cvt_x_kernel(
    const float* __restrict__ x, bf16* __restrict__ xhl)
{
    int t = blockIdx.x * blockDim.x + threadIdx.x;
    if (t >= N_NODES * 32) return;
    int node = t >> 5, j = (t & 31) * 4;
    float4 v = __ldg(reinterpret_cast<const float4*>(x + (size_t)node * 128 + j));
    uint2 hi, lo;
    split4(v, hi, lo);
    *reinterpret_cast<uint2*>(xhl + (size_t)node * 256 + j)       = hi;
    *reinterpret_cast<uint2*>(xhl + (size_t)node * 256 + 128 + j) = lo;
}

__global__ void __launch_bounds__(256) cvt_w_kernel(
    const float* __restrict__ W1l, const float* __restrict__ W1r,
    const float* __restrict__ W2l, const float* __restrict__ W2r,
    const float* __restrict__ W3l, const float* __restrict__ W3r,
    bf16* __restrict__ whl)
{
    int id = blockIdx.x * blockDim.x + threadIdx.x;   // 3*128*64 groups of 4
    if (id >= 3 * 128 * 64) return;
    int l = id / (128 * 64);
    int n = (id / 64) & 127;
    int k = (id & 63) * 4;
    const float* Wl = (l == 0) ? W1l : (l == 1) ? W2l : W3l;
    const float* Wr = (l == 0) ? W1r : (l == 1) ? W2r : W3r;
    float4 v;
    if (k < 128) v = __ldg(reinterpret_cast<const float4*>(Wl + n * 128 + k));
    else         v = __ldg(reinterpret_cast<const float4*>(Wr + n * 128 + k - 128));
    uint2 hi, lo;
    split4(v, hi, lo);
    bf16* row = whl + (size_t)l * 65536 + (size_t)n * 512;
    *reinterpret_cast<uint2*>(row + k)       = hi;
    *reinterpret_cast<uint2*>(row + 256 + k) = lo;
}

// ---------------- CSR build ----------------
__global__ void __launch_bounds__(256) zero_deg_kernel(int* __restrict__ deg)
{
    int i = blockIdx.x * blockDim.x + threadIdx.x;
    if (i < N_NODES) deg[i] = 0;
}
__global__ void __launch_bounds__(256) hist_kernel(
    const int* __restrict__ ei, int* __restrict__ deg)
{
    int e = blockIdx.x * blockDim.x + threadIdx.x;
    if (e >= N_EDGES) return;
    atomicAdd(deg + __ldg(ei + N_EDGES + e), 1);
}
__global__ void __launch_bounds__(1024) scan_kernel(
    const int* __restrict__ deg, int* __restrict__ off, int* __restrict__ cur)
{
    __shared__ int part[1024];
    const int tid = threadIdx.x;
    const int CH = (N_NODES + 1023) / 1024;
    const int start = tid * CH;
    int sum = 0;
    for (int i = 0; i < CH; ++i) {
        int idx = start + i;
        if (idx < N_NODES) sum += deg[idx];
    }
    part[tid] = sum;
    __syncthreads();
    for (int d = 1; d < 1024; d <<= 1) {
        int v = (tid >= d) ? part[tid - d] : 0;
        __syncthreads();
        part[tid] += v;
        __syncthreads();
    }
    int run = tid ? part[tid - 1] : 0;
    for (int i = 0; i < CH; ++i) {
        int idx = start + i;
        if (idx <= N_NODES) {
            off[idx] = run;
            if (idx < N_NODES) cur[idx] = run;
        }
        if (idx < N_NODES) run += deg[idx];
    }
}
__global__ void __launch_bounds__(256) fill_kernel(
    const int* __restrict__ ei, int* __restrict__ cur, int* __restrict__ srcs)
{
    int e = blockIdx.x * blockDim.x + threadIdx.x;
    if (e >= N_EDGES) return;
    int src = __ldg(ei + e);
    int dst = __ldg(ei + N_EDGES + e);
    int pos = atomicAdd(cur + dst, 1);
    srcs[pos] = src;
}

// ---------------- gather aggregation (512B-row hi|lo format) ----------------
// warp per node; lane reads one uint4 of the row (lanes 0-15 hi, 16-31 lo);
// fp32 accumulate; shfl(16) combines hi+lo; lanes 0-15 write hi|lo row.
__global__ void __launch_bounds__(256) aggregate_kernel(
    const bf16* __restrict__ hl,
    const int*  __restrict__ off,
    const int*  __restrict__ srcs,
    bf16*       __restrict__ al)
{
    int node = (blockIdx.x * blockDim.x + threadIdx.x) >> 5;
    int lane = threadIdx.x & 31;
    if (node >= N_NODES) return;
    int b = __ldg(off + node);
    int e = __ldg(off + node + 1);
    float acc[8] = {0.f, 0.f, 0.f, 0.f, 0.f, 0.f, 0.f, 0.f};
    int i = b;
    for (; i + 1 < e; i += 2) {
        int s0 = __ldg(srcs + i);
        int s1 = __ldg(srcs + i + 1);
        uint4 v0 = __ldg(reinterpret_cast<const uint4*>(hl + (size_t)s0 * 256) + lane);
        uint4 v1 = __ldg(reinterpret_cast<const uint4*>(hl + (size_t)s1 * 256) + lane);
        add8(acc, v0);
        add8(acc, v1);
    }
    if (i < e) {
        int s = __ldg(srcs + i);
        uint4 v = __ldg(reinterpret_cast<const uint4*>(hl + (size_t)s * 256) + lane);
        add8(acc, v);
    }
    // combine: lanes 0-15 (hi sums) += lanes 16-31 (lo sums)
    float fin[8];
#pragma unroll
    for (int j = 0; j < 8; ++j)
        fin[j] = acc[j] + __shfl_down_sync(0xffffffffu, acc[j], 16);
    if (lane < 16) {
        uint2 hi0, lo0, hi1, lo1;
        split4(make_float4(fin[0], fin[1], fin[2], fin[3]), hi0, lo0);
        split4(make_float4(fin[4], fin[5], fin[6], fin[7]), hi1, lo1);
        uint4 hi = make_uint4(hi0.x, hi0.y, hi1.x, hi1.y);
        uint4 lo = make_uint4(lo0.x, lo0.y, lo1.x, lo1.y);
        *reinterpret_cast<uint4*>(al + (size_t)node * 256 + lane * 8)       = hi;
        *reinterpret_cast<uint4*>(al + (size_t)node * 256 + 128 + lane * 8) = lo;
    }
}

// ================ conversion-free WMMA bf16x2 SAGE GEMM ================
// CTA tile 128x128; K=256 in 4 chunks of 64 (agg k0/k64, h k0/k64).
// All operands pre-split bf16 hi/lo; tiles stream in via cp.async, 2 stages.
#define LDT 72
#define A_HI_OFF 0
#define A_LO_OFF 18432
#define B_HI_OFF 36864
#define B_LO_OFF 55296
#define STAGE_BYTES 73728
#define SM_TOTAL (2 * STAGE_BYTES)   // 147456

__device__ __forceinline__ void load_chunk(
    int c, uint32_t stg,
    const bf16* aHl, const bf16* hHl, const bf16* wHl,
    int block_row, int tid)
{
    const bf16* A = (c < 2) ? aHl : hHl;
    const int k0 = (c & 1) * 64;
    const int row  = tid >> 1;   // 0..127
    const int part = tid & 1;    // 0=hi, 1=lo
    // A: row record 256 bf16 = [128 hi | 128 lo]; chunk cols k0..k0+63
    const bf16* srcA = A + (size_t)(block_row + row) * 256 + part * 128 + k0;
    uint32_t dA = stg + (part ? A_LO_OFF : A_HI_OFF) + row * (LDT * 2);
#pragma unroll
    for (int i = 0; i < 8; ++i) cp16(dA + i * 16, srcA + i * 8);
    // B: weight record 512 bf16 = [256 hi | 256 lo]; chunk cols c*64..
    const bf16* srcB = wHl + (size_t)row * 512 + part * 256 + c * 64;
    uint32_t dB = stg + (part ? B_LO_OFF : B_HI_OFF) + row * (LDT * 2);
#pragma unroll
    for (int i = 0; i < 8; ++i) cp16(dB + i * 16, srcB + i * 8);
}

__global__ void __launch_bounds__(256)
sage_wmma_kernel(
    const bf16* __restrict__ aHl,
    const bf16* __restrict__ hHl,
    const bf16* __restrict__ wHl,
    const float* __restrict__ bias,
    bf16* __restrict__ oHl,
    int do_relu)
{
    extern __shared__ char smem[];
    const uint32_t sbase = smem_u32(smem);
    const int tid = threadIdx.x;
    const int wid = tid >> 5;
    const int block_row = blockIdx.x * 128;

    const int wm = (wid & 1) * 64;   // 2 m-tiles of 64
    const int wn = (wid >> 1) * 32;  // 4 n-tiles of 32

    wmma::fragment<wmma::accumulator, 16, 16, 16, float> acc[4][2];
#pragma unroll
    for (int i = 0; i < 4; ++i)
#pragma unroll
        for (int j = 0; j < 2; ++j) wmma::fill_fragment(acc[i][j], 0.f);

    load_chunk(0, sbase, aHl, hHl, wHl, block_row, tid);
    CP_COMMIT();
    load_chunk(1, sbase + STAGE_BYTES, aHl, hHl, wHl, block_row, tid);
    CP_COMMIT();

#pragma unroll 1
    for (int c = 0; c < 4; ++c) {
        if (c < 3) CP_WAIT1(); else CP_WAIT0();
        __syncthreads();

        char* st = smem + (c & 1) * STAGE_BYTES;
        const bf16* sAhi = reinterpret_cast<const bf16*>(st + A_HI_OFF);
        const bf16* sAlo = reinterpret_cast<const bf16*>(st + A_LO_OFF);
        const bf16* sBhi = reinterpret_cast<const bf16*>(st + B_HI_OFF);
        const bf16* sBlo = reinterpret_cast<const bf16*>(st + B_LO_OFF);

#pragma unroll
        for (int ks = 0; ks < 4; ++ks) {
            wmma::fragment<wmma::matrix_a, 16, 16, 16, bf16, wmma::row_major> fah[4], fal[4];
#pragma unroll
            for (int i = 0; i < 4; ++i) {
                wmma::load_matrix_sync(fah[i], sAhi + (wm + i * 16) * LDT + ks * 16, LDT);
                wmma::load_matrix_sync(fal[i], sAlo + (wm + i * 16) * LDT + ks * 16, LDT);
            }
#pragma unroll
            for (int j = 0; j < 2; ++j) {
                wmma::fragment<wmma::matrix_b, 16, 16, 16, bf16, wmma::col_major> fbh, fbl;
                wmma::load_matrix_sync(fbh, sBhi + (wn + j * 16) * LDT + ks * 16, LDT);
                wmma::load_matrix_sync(fbl, sBlo + (wn + j * 16) * LDT + ks * 16, LDT);
#pragma unroll
                for (int i = 0; i < 4; ++i) {
                    wmma::mma_sync(acc[i][j], fah[i], fbh, acc[i][j]);
                    wmma::mma_sync(acc[i][j], fah[i], fbl, acc[i][j]);
                    wmma::mma_sync(acc[i][j], fal[i], fbh, acc[i][j]);
                }
            }
        }
        __syncthreads();
        if (c + 2 < 4) {
            load_chunk(c + 2, sbase + (c & 1) * STAGE_BYTES, aHl, hHl, wHl, block_row, tid);
            CP_COMMIT();
        }
    }

    // ---- epilogue: frags -> SMEM f32 (ldm 132) -> bias/relu -> hi|lo rows ----
    float* sEpi = reinterpret_cast<float*>(smem);
#pragma unroll
    for (int i = 0; i < 4; ++i)
#pragma unroll
        for (int j = 0; j < 2; ++j)
            wmma::store_matrix_sync(sEpi + (wm + i * 16) * 132 + wn + j * 16,
                                    acc[i][j], 132, wmma::mem_row_major);
    __syncthreads();

    {
        const int row  = tid >> 1;
        const int half = (tid & 1) * 64;
        bf16* orow = oHl + (size_t)(block_row + row) * 256;
#pragma unroll
        for (int cb = 0; cb < 64; cb += 8) {
            float4 v0 = *reinterpret_cast<float4*>(sEpi + row * 132 + half + cb);
            float4 v1 = *reinterpret_cast<float4*>(sEpi + row * 132 + half + cb + 4);
            const float4 b0 = *reinterpret_cast<const float4*>(bias + half + cb);
            const float4 b1 = *reinterpret_cast<const float4*>(bias + half + cb + 4);
            v0.x += b0.x; v0.y += b0.y; v0.z += b0.z; v0.w += b0.w;
            v1.x += b1.x; v1.y += b1.y; v1.z += b1.z; v1.w += b1.w;
            if (do_relu) {
                v0.x = fmaxf(v0.x, 0.f); v0.y = fmaxf(v0.y, 0.f);
                v0.z = fmaxf(v0.z, 0.f); v0.w = fmaxf(v0.w, 0.f);
                v1.x = fmaxf(v1.x, 0.f); v1.y = fmaxf(v1.y, 0.f);
                v1.z = fmaxf(v1.z, 0.f); v1.w = fmaxf(v1.w, 0.f);
            }
            uint2 h0, l0, h1, l1;
            split4(v0, h0, l0);
            split4(v1, h1, l1);
            *reinterpret_cast<uint4*>(orow + half + cb)       = make_uint4(h0.x, h0.y, h1.x, h1.y);
            *reinterpret_cast<uint4*>(orow + 128 + half + cb) = make_uint4(l0.x, l0.y, l1.x, l1.y);
        }
    }
}

// ---------------- pooling (hi|lo rows) ----------------
__global__ void __launch_bounds__(256) pool_kernel(
    const bf16* __restrict__ hl,
    const int*  __restrict__ batch,
    float*      __restrict__ pooled)
{
    int node = (blockIdx.x * blockDim.x + threadIdx.x) >> 5;
    int lane = threadIdx.x & 31;
    if (node >= N_NODES) return;
    int g = __ldg(batch + node);
    uint4 v = __ldg(reinterpret_cast<const uint4*>(hl + (size_t)node * 256) + lane);
    float acc[8] = {0.f, 0.f, 0.f, 0.f, 0.f, 0.f, 0.f, 0.f};
    add8(acc, v);
    const int c0 = (lane & 15) * 8;   // lanes 0-15 hi part, 16-31 lo part -> same cols
    float* ap = pooled + (size_t)g * HIDDEN + c0;
    asm volatile("red.global.add.v4.f32 [%0], {%1,%2,%3,%4};"
                 :: "l"(ap), "f"(acc[0]), "f"(acc[1]), "f"(acc[2]), "f"(acc[3]) : "memory");
    asm volatile("red.global.add.v4.f32 [%0], {%1,%2,%3,%4};"
                 :: "l"(ap + 4), "f"(acc[4]), "f"(acc[5]), "f"(acc[6]), "f"(acc[7]) : "memory");
}

// ---------------- output head ----------------
__global__ void out_kernel(
    const float* __restrict__ pooled,
    const float* __restrict__ Wout,
    const float* __restrict__ bout,
    float*       __restrict__ out)
{
    int idx = blockIdx.x * blockDim.x + threadIdx.x;
    if (idx >= NUM_GRAPHS * N_CLASSES) return;
    int g = idx / N_CLASSES;
    int c = idx % N_CLASSES;
    float s = __ldg(bout + c);
    const float* p = pooled + (size_t)g * HIDDEN;
    const float* w = Wout + (size_t)c * HIDDEN;
#pragma unroll 8
    for (int k = 0; k < HIDDEN; ++k) s = fmaf(p[k], w[k], s);
    out[idx] = s;
}

// ---------------- launch ----------------
extern "C" void kernel_launch(void* const* d_in, const int* in_sizes, int n_in,
                              void* d_out, int out_size)
{
    const float* x     = (const float*)d_in[0];
    const int*   ei    = (const int*)  d_in[1];
    const int*   batch = (const int*)  d_in[2];
    const float* W1l = (const float*)d_in[3];
    const float* b1  = (const float*)d_in[4];
    const float* W1r = (const float*)d_in[5];
    const float* W2l = (const float*)d_in[6];
    const float* b2  = (const float*)d_in[7];
    const float* W2r = (const float*)d_in[8];
    const float* W3l = (const float*)d_in[9];
    const float* b3  = (const float*)d_in[10];
    const float* W3r = (const float*)d_in[11];
    const float* Wout = (const float*)d_in[12];
    const float* bout = (const float*)d_in[13];
    float* out = (float*)d_out;

    bf16 *xhl, *ahl, *h0hl, *h1hl, *whl;
    float *pooled;
    int *deg, *off, *cur, *srcs;
    cudaGetSymbolAddress((void**)&xhl,  g_xhl);
    cudaGetSymbolAddress((void**)&ahl,  g_ahl);
    cudaGetSymbolAddress((void**)&h0hl, g_h0hl);
    cudaGetSymbolAddress((void**)&h1hl, g_h1hl);
    cudaGetSymbolAddress((void**)&whl,  g_whl);
    cudaGetSymbolAddress((void**)&pooled, g_pooled);
    cudaGetSymbolAddress((void**)&deg,  g_deg);
    cudaGetSymbolAddress((void**)&off,  g_off);
    cudaGetSymbolAddress((void**)&cur,  g_cur);
    cudaGetSymbolAddress((void**)&srcs, g_srcs);

    cudaFuncSetAttribute(sage_wmma_kernel,
                         cudaFuncAttributeMaxDynamicSharedMemorySize, SM_TOTAL);

    const int edge_blocks = (N_EDGES + 255) / 256;
    const int node_blocks = (N_NODES + 255) / 256;
    const int gemm_blocks = N_PAD / 128;   // 782
    const int warp_blocks = (N_NODES * 32 + 255) / 256;

    // one-time conversions
    cvt_x_kernel<<<(N_NODES * 32 + 255) / 256, 256>>>(x, xhl);
    cvt_w_kernel<<<(3 * 128 * 64 + 255) / 256, 256>>>(W1l, W1r, W2l, W2r, W3l, W3r, whl);

    // CSR build
    zero_deg_kernel<<<node_blocks, 256>>>(deg);
    hist_kernel<<<edge_blocks, 256>>>(ei, deg);
    scan_kernel<<<1, 1024>>>(deg, off, cur);
    fill_kernel<<<edge_blocks, 256>>>(ei, cur, srcs);

    // layer 1: x -> h0
    aggregate_kernel<<<warp_blocks, 256>>>(xhl, off, srcs, ahl);
    sage_wmma_kernel<<<gemm_blocks, 256, SM_TOTAL>>>(ahl, xhl, whl, b1, h0hl, 1);

    // layer 2: h0 -> h1
    aggregate_kernel<<<warp_blocks, 256>>>(h0hl, off, srcs, ahl);
    sage_wmma_kernel<<<gemm_blocks, 256, SM_TOTAL>>>(ahl, h0hl, whl + 65536, b2, h1hl, 1);

    // layer 3: h1 -> h0 (no relu)
    aggregate_kernel<<<warp_blocks, 256>>>(h1hl, off, srcs, ahl);
    sage_wmma_kernel<<<gemm_blocks, 256, SM_TOTAL>>>(ahl, h1hl, whl + 131072, b3, h0hl, 0);

    // pool + head
    cudaMemsetAsync(pooled, 0, NUM_GRAPHS * HIDDEN * sizeof(float));
    pool_kernel<<<warp_blocks, 256>>>(h0hl, batch, pooled);
    out_kernel<<<(NUM_GRAPHS * N_CLASSES + 127) / 128, 128>>>(pooled, Wout, bout, out);
}

// round 10
// speedup vs baseline: 1.4638x; 1.4638x over previous
#include <cuda_runtime.h>
#include <cuda_bf16.h>
#include <mma.h>
#include <cstdint>

using namespace nvcuda;

#define N_NODES   100000
#define N_EDGES   1600000
#define D_FEAT    128
#define HIDDEN    128
#define N_CLASSES 10
#define NUM_GRAPHS 64
#define N_PAD     100096   // 782 * 128, full-tile padding for direct wmma stores

typedef __nv_bfloat16 bf16;
typedef __nv_bfloat162 bf162;

#define LDT 72             // padded bf16 row length for 64-col tiles

// ---------------- scratch (no allocs allowed) ----------------
__device__ float g_agg[(size_t)N_PAD * 128];
__device__ float g_h1 [(size_t)N_PAD * 128];
__device__ float g_h2 [(size_t)N_PAD * 128];
// weights pre-split, chunk-tiled SMEM-ready: [3 layers][4 chunks][128 n][LDT]
__device__ bf16  g_whi[3 * 4 * 128 * LDT];
__device__ bf16  g_wlo[3 * 4 * 128 * LDT];
__device__ float g_pooled[NUM_GRAPHS * HIDDEN];
__device__ int   g_deg [N_NODES];
__device__ int   g_off [N_NODES + 1];
__device__ int   g_cur [N_NODES];
__device__ int   g_srcs[N_EDGES];

// ---------------- helpers ----------------
__device__ __forceinline__ uint32_t smem_u32(const void* p) {
    uint32_t a;
    asm("{ .reg .u64 t; cvta.to.shared.u64 t, %1; cvt.u32.u64 %0, t; }" : "=r"(a) : "l"(p));
    return a;
}
__device__ __forceinline__ void cp16(uint32_t dst, const void* src) {
    asm volatile("cp.async.cg.shared.global [%0], [%1], 16;" :: "r"(dst), "l"(src));
}
#define CP_COMMIT() asm volatile("cp.async.commit_group;" ::: "memory")
#define CP_WAIT1()  asm volatile("cp.async.wait_group 1;" ::: "memory")
#define CP_WAIT0()  asm volatile("cp.async.wait_group 0;" ::: "memory")

__device__ __forceinline__ void split4(float4 v, uint2& hi, uint2& lo) {
    bf162 h0, h1, l0, l1;
    h0.x = __float2bfloat16(v.x); h0.y = __float2bfloat16(v.y);
    h1.x = __float2bfloat16(v.z); h1.y = __float2bfloat16(v.w);
    l0.x = __float2bfloat16(v.x - __bfloat162float(h0.x));
    l0.y = __float2bfloat16(v.y - __bfloat162float(h0.y));
    l1.x = __float2bfloat16(v.z - __bfloat162float(h1.x));
    l1.y = __float2bfloat16(v.w - __bfloat162float(h1.y));
    hi.x = *reinterpret_cast<uint32_t*>(&h0); hi.y = *reinterpret_cast<uint32_t*>(&h1);
    lo.x = *reinterpret_cast<uint32_t*>(&l0); lo.y = *reinterpret_cast<uint32_t*>(&l1);
}

// ---------------- weight conversion (one-time) ----------------
// W record per (layer, chunk c, out-neuron n): 64 k-cols at [((l*4+c)*128+n)*LDT]
__global__ void __launch_bounds__(256) cvt_w_kernel(
    const float* __restrict__ W1l, const float* __restrict__ W1r,
    const float* __restrict__ W2l, const float* __restrict__ W2r,
    const float* __restrict__ W3l, const float* __restrict__ W3r,
    bf16* __restrict__ whi, bf16* __restrict__ wlo)
{
    int id = blockIdx.x * blockDim.x + threadIdx.x;   // 3*128*64 quads
    if (id >= 3 * 128 * 64) return;
    int l = id / (128 * 64);
    int n = (id / 64) % 128;
    int k = (id & 63) * 4;            // 0..252
    const float* Wl = (l == 0) ? W1l : (l == 1) ? W2l : W3l;
    const float* Wr = (l == 0) ? W1r : (l == 1) ? W2r : W3r;
    float4 v;
    if (k < 128) v = __ldg(reinterpret_cast<const float4*>(Wl + n * 128 + k));
    else         v = __ldg(reinterpret_cast<const float4*>(Wr + n * 128 + k - 128));
    uint2 hi, lo;
    split4(v, hi, lo);
    int c  = k >> 6;
    int kk = k & 63;
    size_t dst = ((size_t)(l * 4 + c) * 128 + n) * LDT + kk;
    *reinterpret_cast<uint2*>(whi + dst) = hi;
    *reinterpret_cast<uint2*>(wlo + dst) = lo;
}

// ---------------- CSR build ----------------
__global__ void __launch_bounds__(256) zero_deg_kernel(int* __restrict__ deg)
{
    int i = blockIdx.x * blockDim.x + threadIdx.x;
    if (i < N_NODES) deg[i] = 0;
}
__global__ void __launch_bounds__(256) hist_kernel(
    const int* __restrict__ ei, int* __restrict__ deg)
{
    int e = blockIdx.x * blockDim.x + threadIdx.x;
    if (e >= N_EDGES) return;
    atomicAdd(deg + __ldg(ei + N_EDGES + e), 1);
}
__global__ void __launch_bounds__(1024) scan_kernel(
    const int* __restrict__ deg, int* __restrict__ off, int* __restrict__ cur)
{
    __shared__ int part[1024];
    const int tid = threadIdx.x;
    const int CH = (N_NODES + 1023) / 1024;
    const int start = tid * CH;
    int sum = 0;
    for (int i = 0; i < CH; ++i) {
        int idx = start + i;
        if (idx < N_NODES) sum += deg[idx];
    }
    part[tid] = sum;
    __syncthreads();
    for (int d = 1; d < 1024; d <<= 1) {
        int v = (tid >= d) ? part[tid - d] : 0;
        __syncthreads();
        part[tid] += v;
        __syncthreads();
    }
    int run = tid ? part[tid - 1] : 0;
    for (int i = 0; i < CH; ++i) {
        int idx = start + i;
        if (idx <= N_NODES) {
            off[idx] = run;
            if (idx < N_NODES) cur[idx] = run;
        }
        if (idx < N_NODES) run += deg[idx];
    }
}
__global__ void __launch_bounds__(256) fill_kernel(
    const int* __restrict__ ei, int* __restrict__ cur, int* __restrict__ srcs)
{
    int e = blockIdx.x * blockDim.x + threadIdx.x;
    if (e >= N_EDGES) return;
    int src = __ldg(ei + e);
    int dst = __ldg(ei + N_EDGES + e);
    int pos = atomicAdd(cur + dst, 1);
    srcs[pos] = src;
}

// ---------------- gather aggregation (fp32, R7-verbatim) ----------------
__global__ void __launch_bounds__(256) aggregate_kernel(
    const float* __restrict__ h,
    const int*   __restrict__ off,
    const int*   __restrict__ srcs,
    float*       __restrict__ agg)
{
    int node = (blockIdx.x * blockDim.x + threadIdx.x) >> 5;
    int lane = threadIdx.x & 31;
    if (node >= N_NODES) return;
    int b = __ldg(off + node);
    int e = __ldg(off + node + 1);
    float4 acc = make_float4(0.f, 0.f, 0.f, 0.f);
    int i = b;
    for (; i + 3 < e; i += 4) {
        int s0 = __ldg(srcs + i + 0);
        int s1 = __ldg(srcs + i + 1);
        int s2 = __ldg(srcs + i + 2);
        int s3 = __ldg(srcs + i + 3);
        float4 v0 = __ldg(reinterpret_cast<const float4*>(h + (size_t)s0 * 128) + lane);
        float4 v1 = __ldg(reinterpret_cast<const float4*>(h + (size_t)s1 * 128) + lane);
        float4 v2 = __ldg(reinterpret_cast<const float4*>(h + (size_t)s2 * 128) + lane);
        float4 v3 = __ldg(reinterpret_cast<const float4*>(h + (size_t)s3 * 128) + lane);
        acc.x += (v0.x + v1.x) + (v2.x + v3.x);
        acc.y += (v0.y + v1.y) + (v2.y + v3.y);
        acc.z += (v0.z + v1.z) + (v2.z + v3.z);
        acc.w += (v0.w + v1.w) + (v2.w + v3.w);
    }
    for (; i < e; ++i) {
        int s = __ldg(srcs + i);
        float4 v = __ldg(reinterpret_cast<const float4*>(h + (size_t)s * 128) + lane);
        acc.x += v.x; acc.y += v.y; acc.z += v.z; acc.w += v.w;
    }
    *(reinterpret_cast<float4*>(agg + (size_t)node * 128) + lane) = acc;
}

// ================ WMMA bf16x2 SAGE GEMM ================
// A (activations) converted in-kernel as R7; B (weights) pre-split,
// streamed via cp.async double-buffered.
// CTA 128x128, 8 warps in 2(m) x 4(n), warp tile 64x32.
// K = 256 in 4 chunks of 64: [agg 0-63][agg 64-127][h 0-63][h 64-127]
#define A_HI_OFF 0
#define A_LO_OFF 18432
#define B_BASE   36864
#define B_STAGE  36864              // hi 18432 + lo 18432
#define SM_TOTAL (B_BASE + 2 * B_STAGE)   // 110592 -> 2 CTAs/SM

__device__ __forceinline__ void load_B(
    int c, uint32_t stg, const bf16* whi, const bf16* wlo, int tid)
{
    const int r = tid >> 1;          // 0..127 (n)
    const int half = (tid & 1) * 32; // k offset within chunk
    const bf16* srcH = whi + ((size_t)c * 128 + r) * LDT + half;
    const bf16* srcL = wlo + ((size_t)c * 128 + r) * LDT + half;
    uint32_t dH = stg + r * (LDT * 2) + half * 2;
    uint32_t dL = stg + 18432 + r * (LDT * 2) + half * 2;
#pragma unroll
    for (int i = 0; i < 4; ++i) {
        cp16(dH + i * 16, srcH + i * 8);
        cp16(dL + i * 16, srcL + i * 8);
    }
}

__global__ void __launch_bounds__(256)
sage_wmma_kernel(
    const float* __restrict__ agg,
    const float* __restrict__ h,
    const bf16*  __restrict__ whi,   // layer base, chunk-tiled
    const bf16*  __restrict__ wlo,
    const float* __restrict__ bias,
    float*       __restrict__ out,   // padded to N_PAD rows
    int do_relu)
{
    extern __shared__ char smem[];
    const uint32_t sbase = smem_u32(smem);
    bf16* sAhi = reinterpret_cast<bf16*>(smem + A_HI_OFF);
    bf16* sAlo = reinterpret_cast<bf16*>(smem + A_LO_OFF);

    const int tid = threadIdx.x;
    const int wid = tid >> 5;
    const int block_row = blockIdx.x * 128;

    // tile-load mapping: thread owns 32 contiguous cols of one A row
    const int row  = tid >> 1;
    const int c0   = (tid & 1) * 32;
    const bool aok = (block_row + row) < N_NODES;

    const int wm = (wid & 1) * 64;
    const int wn = (wid >> 1) * 32;

    wmma::fragment<wmma::accumulator, 16, 16, 16, float> acc[4][2];
#pragma unroll
    for (int i = 0; i < 4; ++i)
#pragma unroll
        for (int j = 0; j < 2; ++j) wmma::fill_fragment(acc[i][j], 0.f);

    // prime B pipeline: chunks 0,1
    load_B(0, sbase + B_BASE,           whi, wlo, tid);
    CP_COMMIT();
    load_B(1, sbase + B_BASE + B_STAGE, whi, wlo, tid);
    CP_COMMIT();

    // prefetch A chunk 0
    float4 av[8];
    {
        const float* ap = agg + (size_t)(block_row + row) * 128 + c0;
#pragma unroll
        for (int j = 0; j < 8; ++j)
            av[j] = aok ? __ldg(reinterpret_cast<const float4*>(ap) + j)
                        : make_float4(0.f, 0.f, 0.f, 0.f);
    }

#pragma unroll 1
    for (int c = 0; c < 4; ++c) {
        // convert prefetched A -> bf16 hi/lo, store to SMEM
#pragma unroll
        for (int j = 0; j < 8; ++j) {
            int eoff = row * LDT + c0 + j * 4;
            uint2 hi, lo;
            split4(av[j], hi, lo);
            *reinterpret_cast<uint2*>(sAhi + eoff) = hi;
            *reinterpret_cast<uint2*>(sAlo + eoff) = lo;
        }
        if (c < 3) CP_WAIT1(); else CP_WAIT0();
        __syncthreads();

        // prefetch next A chunk (overlaps with MMA below)
        if (c < 3) {
            const int nc = c + 1;
            const float* Asrc = (nc < 2) ? agg : h;
            const int k0 = (nc & 1) * 64;
            const float* ap = Asrc + (size_t)(block_row + row) * 128 + k0 + c0;
#pragma unroll
            for (int j = 0; j < 8; ++j)
                av[j] = aok ? __ldg(reinterpret_cast<const float4*>(ap) + j)
                            : make_float4(0.f, 0.f, 0.f, 0.f);
        }

        const char* st = smem + B_BASE + (c & 1) * B_STAGE;
        const bf16* sBhi = reinterpret_cast<const bf16*>(st);
        const bf16* sBlo = reinterpret_cast<const bf16*>(st + 18432);

#pragma unroll
        for (int ks = 0; ks < 4; ++ks) {
            wmma::fragment<wmma::matrix_a, 16, 16, 16, bf16, wmma::row_major> fah[4], fal[4];
#pragma unroll
            for (int i = 0; i < 4; ++i) {
                wmma::load_matrix_sync(fah[i], sAhi + (wm + i * 16) * LDT + ks * 16, LDT);
                wmma::load_matrix_sync(fal[i], sAlo + (wm + i * 16) * LDT + ks * 16, LDT);
            }
#pragma unroll
            for (int j = 0; j < 2; ++j) {
                wmma::fragment<wmma::matrix_b, 16, 16, 16, bf16, wmma::col_major> fbh, fbl;
                wmma::load_matrix_sync(fbh, sBhi + (wn + j * 16) * LDT + ks * 16, LDT);
                wmma::load_matrix_sync(fbl, sBlo + (wn + j * 16) * LDT + ks * 16, LDT);
#pragma unroll
                for (int i = 0; i < 4; ++i) {
                    wmma::mma_sync(acc[i][j], fah[i], fbh, acc[i][j]);
                    wmma::mma_sync(acc[i][j], fah[i], fbl, acc[i][j]);
                    wmma::mma_sync(acc[i][j], fal[i], fbh, acc[i][j]);
                }
            }
        }
        __syncthreads();
        if (c + 2 < 4) {
            load_B(c + 2, sbase + B_BASE + (c & 1) * B_STAGE, whi, wlo, tid);
            CP_COMMIT();
        }
    }

    // ---- epilogue: replicated bias in reused A-SMEM, in-fragment add, direct store ----
    float* sBias = reinterpret_cast<float*>(smem);
    for (int idx = tid; idx < 16 * 128; idx += 256)
        sBias[idx] = __ldg(bias + (idx & 127));
    __syncthreads();

#pragma unroll
    for (int j = 0; j < 2; ++j) {
        wmma::fragment<wmma::accumulator, 16, 16, 16, float> bf;
        wmma::load_matrix_sync(bf, sBias + wn + j * 16, 128, wmma::mem_row_major);
#pragma unroll
        for (int i = 0; i < 4; ++i) {
#pragma unroll
            for (int e = 0; e < acc[i][j].num_elements; ++e) {
                float v = acc[i][j].x[e] + bf.x[e];
                acc[i][j].x[e] = do_relu ? fmaxf(v, 0.f) : v;
            }
            float* op = out + (size_t)(block_row + wm + i * 16) * 128 + wn + j * 16;
            wmma::store_matrix_sync(op, acc[i][j], 128, wmma::mem_row_major);
        }
    }
}

// ---------------- pooling ----------------
__global__ void __launch_bounds__(256) pool_kernel(
    const float* __restrict__ h,
    const int*   __restrict__ batch,
    float*       __restrict__ pooled)
{
    int node = (blockIdx.x * blockDim.x + threadIdx.x) >> 5;
    int lane = threadIdx.x & 31;
    if (node >= N_NODES) return;
    int g = __ldg(batch + node);
    float4 v = __ldg(reinterpret_cast<const float4*>(h + (size_t)node * 128) + lane);
    float* ap = pooled + (size_t)g * HIDDEN + lane * 4;
    asm volatile("red.global.add.v4.f32 [%0], {%1,%2,%3,%4};"
                 :: "l"(ap), "f"(v.x), "f"(v.y), "f"(v.z), "f"(v.w) : "memory");
}

// ---------------- output head ----------------
__global__ void out_kernel(
    const float* __restrict__ pooled,
    const float* __restrict__ Wout,
    const float* __restrict__ bout,
    float*       __restrict__ out)
{
    int idx = blockIdx.x * blockDim.x + threadIdx.x;
    if (idx >= NUM_GRAPHS * N_CLASSES) return;
    int g = idx / N_CLASSES;
    int c = idx % N_CLASSES;
    float s = __ldg(bout + c);
    const float* p = pooled + (size_t)g * HIDDEN;
    const float* w = Wout + (size_t)c * HIDDEN;
#pragma unroll 8
    for (int k = 0; k < HIDDEN; ++k) s = fmaf(p[k], w[k], s);
    out[idx] = s;
}

// ---------------- launch ----------------
extern "C" void kernel_launch(void* const* d_in, const int* in_sizes, int n_in,
                              void* d_out, int out_size)
{
    const float* x     = (const float*)d_in[0];
    const int*   ei    = (const int*)  d_in[1];
    const int*   batch = (const int*)  d_in[2];
    const float* W1l = (const float*)d_in[3];
    const float* b1  = (const float*)d_in[4];
    const float* W1r = (const float*)d_in[5];
    const float* W2l = (const float*)d_in[6];
    const float* b2  = (const float*)d_in[7];
    const float* W2r = (const float*)d_in[8];
    const float* W3l = (const float*)d_in[9];
    const float* b3  = (const float*)d_in[10];
    const float* W3r = (const float*)d_in[11];
    const float* Wout = (const float*)d_in[12];
    const float* bout = (const float*)d_in[13];
    float* out = (float*)d_out;

    float *agg, *h1, *h2, *pooled;
    bf16 *whi, *wlo;
    int *deg, *off, *cur, *srcs;
    cudaGetSymbolAddress((void**)&agg,    g_agg);
    cudaGetSymbolAddress((void**)&h1,     g_h1);
    cudaGetSymbolAddress((void**)&h2,     g_h2);
    cudaGetSymbolAddress((void**)&whi,    g_whi);
    cudaGetSymbolAddress((void**)&wlo,    g_wlo);
    cudaGetSymbolAddress((void**)&pooled, g_pooled);
    cudaGetSymbolAddress((void**)&deg,    g_deg);
    cudaGetSymbolAddress((void**)&off,    g_off);
    cudaGetSymbolAddress((void**)&cur,    g_cur);
    cudaGetSymbolAddress((void**)&srcs,   g_srcs);

    cudaFuncSetAttribute(sage_wmma_kernel,
                         cudaFuncAttributeMaxDynamicSharedMemorySize, SM_TOTAL);

    const int edge_blocks = (N_EDGES + 255) / 256;
    const int node_blocks = (N_NODES + 255) / 256;
    const int gemm_blocks = N_PAD / 128;   // 782
    const int warp_blocks = (N_NODES * 32 + 255) / 256;
    const int WSTRIDE = 4 * 128 * LDT;     // per-layer weight stride

    // one-time weight conversion
    cvt_w_kernel<<<(3 * 128 * 64 + 255) / 256, 256>>>(W1l, W1r, W2l, W2r, W3l, W3r, whi, wlo);

    // CSR build (once, reused for all 3 layers)
    zero_deg_kernel<<<node_blocks, 256>>>(deg);
    hist_kernel<<<edge_blocks, 256>>>(ei, deg);
    scan_kernel<<<1, 1024>>>(deg, off, cur);
    fill_kernel<<<edge_blocks, 256>>>(ei, cur, srcs);

    // layer 1: x -> h1
    aggregate_kernel<<<warp_blocks, 256>>>(x, off, srcs, agg);
    sage_wmma_kernel<<<gemm_blocks, 256, SM_TOTAL>>>(agg, x, whi, wlo, b1, h1, 1);

    // layer 2: h1 -> h2
    aggregate_kernel<<<warp_blocks, 256>>>(h1, off, srcs, agg);
    sage_wmma_kernel<<<gemm_blocks, 256, SM_TOTAL>>>(agg, h1, whi + WSTRIDE, wlo + WSTRIDE, b2, h2, 1);

    // layer 3: h2 -> h1 (no relu)
    aggregate_kernel<<<warp_blocks, 256>>>(h2, off, srcs, agg);
    sage_wmma_kernel<<<gemm_blocks, 256, SM_TOTAL>>>(agg, h2, whi + 2 * WSTRIDE, wlo + 2 * WSTRIDE, b3, h1, 0);

    // pool + head
    cudaMemsetAsync(pooled, 0, NUM_GRAPHS * HIDDEN * sizeof(float));
    pool_kernel<<<warp_blocks, 256>>>(h1, batch, pooled);
    out_kernel<<<(NUM_GRAPHS * N_CLASSES + 127) / 128, 128>>>(pooled, Wout, bout, out);
}

// round 11
// speedup vs baseline: 1.7796x; 1.2158x over previous
#include <cuda_runtime.h>
#include <cuda_bf16.h>
#include <mma.h>
#include <cstdint>

using namespace nvcuda;

#define N_NODES   100000
#define N_EDGES   1600000
#define D_FEAT    128
#define HIDDEN    128
#define N_CLASSES 10
#define NUM_GRAPHS 64
#define N_PAD     100096   // 782 * 128, full-tile padding for direct wmma stores
#define NBLK      391      // ceil(N_NODES / 256)

typedef __nv_bfloat16 bf16;
typedef __nv_bfloat162 bf162;

#define LDT 72             // padded bf16 row length for 64-col tiles

// ---------------- scratch (no allocs allowed) ----------------
__device__ float g_agg[(size_t)N_PAD * 128];
__device__ float g_h1 [(size_t)N_PAD * 128];
__device__ float g_h2 [(size_t)N_PAD * 128];
// weights pre-split, chunk-tiled SMEM-ready: [3 layers][4 chunks][128 n][LDT]
__device__ bf16  g_whi[3 * 4 * 128 * LDT];
__device__ bf16  g_wlo[3 * 4 * 128 * LDT];
__device__ float g_pooled[NUM_GRAPHS * HIDDEN];
__device__ int   g_deg [N_NODES];
__device__ int   g_off [N_NODES + 1];
__device__ int   g_cur [N_NODES];
__device__ int   g_srcs[N_EDGES];
__device__ int   g_blksum[NBLK];
__device__ int   g_blkoff[NBLK];

// ---------------- helpers ----------------
__device__ __forceinline__ uint32_t smem_u32(const void* p) {
    uint32_t a;
    asm("{ .reg .u64 t; cvta.to.shared.u64 t, %1; cvt.u32.u64 %0, t; }" : "=r"(a) : "l"(p));
    return a;
}
__device__ __forceinline__ void cp16(uint32_t dst, const void* src) {
    asm volatile("cp.async.cg.shared.global [%0], [%1], 16;" :: "r"(dst), "l"(src));
}
#define CP_COMMIT() asm volatile("cp.async.commit_group;" ::: "memory")
#define CP_WAIT1()  asm volatile("cp.async.wait_group 1;" ::: "memory")
#define CP_WAIT0()  asm volatile("cp.async.wait_group 0;" ::: "memory")

__device__ __forceinline__ void split4(float4 v, uint2& hi, uint2& lo) {
    bf162 h0, h1, l0, l1;
    h0.x = __float2bfloat16(v.x); h0.y = __float2bfloat16(v.y);
    h1.x = __float2bfloat16(v.z); h1.y = __float2bfloat16(v.w);
    l0.x = __float2bfloat16(v.x - __bfloat162float(h0.x));
    l0.y = __float2bfloat16(v.y - __bfloat162float(h0.y));
    l1.x = __float2bfloat16(v.z - __bfloat162float(h1.x));
    l1.y = __float2bfloat16(v.w - __bfloat162float(h1.y));
    hi.x = *reinterpret_cast<uint32_t*>(&h0); hi.y = *reinterpret_cast<uint32_t*>(&h1);
    lo.x = *reinterpret_cast<uint32_t*>(&l0); lo.y = *reinterpret_cast<uint32_t*>(&l1);
}

// ---------------- weight conversion (one-time) ----------------
__global__ void __launch_bounds__(256) cvt_w_kernel(
    const float* __restrict__ W1l, const float* __restrict__ W1r,
    const float* __restrict__ W2l, const float* __restrict__ W2r,
    const float* __restrict__ W3l, const float* __restrict__ W3r,
    bf16* __restrict__ whi, bf16* __restrict__ wlo)
{
    int id = blockIdx.x * blockDim.x + threadIdx.x;   // 3*128*64 quads
    if (id >= 3 * 128 * 64) return;
    int l = id / (128 * 64);
    int n = (id / 64) % 128;
    int k = (id & 63) * 4;            // 0..252
    const float* Wl = (l == 0) ? W1l : (l == 1) ? W2l : W3l;
    const float* Wr = (l == 0) ? W1r : (l == 1) ? W2r : W3r;
    float4 v;
    if (k < 128) v = __ldg(reinterpret_cast<const float4*>(Wl + n * 128 + k));
    else         v = __ldg(reinterpret_cast<const float4*>(Wr + n * 128 + k - 128));
    uint2 hi, lo;
    split4(v, hi, lo);
    int c  = k >> 6;
    int kk = k & 63;
    size_t dst = ((size_t)(l * 4 + c) * 128 + n) * LDT + kk;
    *reinterpret_cast<uint2*>(whi + dst) = hi;
    *reinterpret_cast<uint2*>(wlo + dst) = lo;
}

// ---------------- CSR build ----------------
__global__ void __launch_bounds__(256) zero_deg_kernel(int* __restrict__ deg)
{
    int i = blockIdx.x * blockDim.x + threadIdx.x;
    if (i < N_NODES) deg[i] = 0;
}
__global__ void __launch_bounds__(256) hist_kernel(
    const int* __restrict__ ei, int* __restrict__ deg)
{
    int e = blockIdx.x * blockDim.x + threadIdx.x;
    if (e >= N_EDGES) return;
    atomicAdd(deg + __ldg(ei + N_EDGES + e), 1);
}

// --- multi-block scan, step 1: per-block sums of deg ---
__global__ void __launch_bounds__(256) partial_kernel(
    const int* __restrict__ deg, int* __restrict__ blksum)
{
    __shared__ int wsum[8];
    int i = blockIdx.x * 256 + threadIdx.x;
    int v = (i < N_NODES) ? deg[i] : 0;
#pragma unroll
    for (int d = 16; d > 0; d >>= 1) v += __shfl_down_sync(0xffffffffu, v, d);
    if ((threadIdx.x & 31) == 0) wsum[threadIdx.x >> 5] = v;
    __syncthreads();
    if (threadIdx.x < 8) {
        int s = wsum[threadIdx.x];
#pragma unroll
        for (int d = 4; d > 0; d >>= 1) s += __shfl_down_sync(0xffu, s, d);
        if (threadIdx.x == 0) blksum[blockIdx.x] = s;
    }
}

// --- step 2: exclusive scan of 391 block sums (single small block) ---
__global__ void __launch_bounds__(512) scan_blocks_kernel(
    const int* __restrict__ blksum, int* __restrict__ blkoff)
{
    __shared__ int sh[512];
    int t = threadIdx.x;
    sh[t] = (t < NBLK) ? blksum[t] : 0;
    __syncthreads();
#pragma unroll
    for (int d = 1; d < 512; d <<= 1) {
        int v = (t >= d) ? sh[t - d] : 0;
        __syncthreads();
        sh[t] += v;
        __syncthreads();
    }
    if (t < NBLK) blkoff[t] = sh[t] - blksum[t];   // exclusive
}

// --- step 3: per-block scan of deg + base offset -> off, cur ---
__global__ void __launch_bounds__(256) fill_off_kernel(
    const int* __restrict__ deg, const int* __restrict__ blkoff,
    int* __restrict__ off, int* __restrict__ cur)
{
    __shared__ int sh[256];
    int t = threadIdx.x;
    int i = blockIdx.x * 256 + t;
    int v = (i < N_NODES) ? deg[i] : 0;
    sh[t] = v;
    __syncthreads();
#pragma unroll
    for (int d = 1; d < 256; d <<= 1) {
        int u = (t >= d) ? sh[t - d] : 0;
        __syncthreads();
        sh[t] += u;
        __syncthreads();
    }
    if (i < N_NODES) {
        int excl = blkoff[blockIdx.x] + sh[t] - v;
        off[i] = excl;
        cur[i] = excl;
    }
    if (blockIdx.x == 0 && t == 0) off[N_NODES] = N_EDGES;
}

__global__ void __launch_bounds__(256) fill_kernel(
    const int* __restrict__ ei, int* __restrict__ cur, int* __restrict__ srcs)
{
    int e = blockIdx.x * blockDim.x + threadIdx.x;
    if (e >= N_EDGES) return;
    int src = __ldg(ei + e);
    int dst = __ldg(ei + N_EDGES + e);
    int pos = atomicAdd(cur + dst, 1);
    srcs[pos] = src;
}

// ---------------- gather aggregation (fp32) ----------------
__global__ void __launch_bounds__(256) aggregate_kernel(
    const float* __restrict__ h,
    const int*   __restrict__ off,
    const int*   __restrict__ srcs,
    float*       __restrict__ agg)
{
    int node = (blockIdx.x * blockDim.x + threadIdx.x) >> 5;
    int lane = threadIdx.x & 31;
    if (node >= N_NODES) return;
    int b = __ldg(off + node);
    int e = __ldg(off + node + 1);
    float4 acc = make_float4(0.f, 0.f, 0.f, 0.f);
    int i = b;
    for (; i + 3 < e; i += 4) {
        int s0 = __ldg(srcs + i + 0);
        int s1 = __ldg(srcs + i + 1);
        int s2 = __ldg(srcs + i + 2);
        int s3 = __ldg(srcs + i + 3);
        float4 v0 = __ldg(reinterpret_cast<const float4*>(h + (size_t)s0 * 128) + lane);
        float4 v1 = __ldg(reinterpret_cast<const float4*>(h + (size_t)s1 * 128) + lane);
        float4 v2 = __ldg(reinterpret_cast<const float4*>(h + (size_t)s2 * 128) + lane);
        float4 v3 = __ldg(reinterpret_cast<const float4*>(h + (size_t)s3 * 128) + lane);
        acc.x += (v0.x + v1.x) + (v2.x + v3.x);
        acc.y += (v0.y + v1.y) + (v2.y + v3.y);
        acc.z += (v0.z + v1.z) + (v2.z + v3.z);
        acc.w += (v0.w + v1.w) + (v2.w + v3.w);
    }
    for (; i < e; ++i) {
        int s = __ldg(srcs + i);
        float4 v = __ldg(reinterpret_cast<const float4*>(h + (size_t)s * 128) + lane);
        acc.x += v.x; acc.y += v.y; acc.z += v.z; acc.w += v.w;
    }
    *(reinterpret_cast<float4*>(agg + (size_t)node * 128) + lane) = acc;
}

// ================ WMMA bf16x2 SAGE GEMM (R10) ================
#define A_HI_OFF 0
#define A_LO_OFF 18432
#define B_BASE   36864
#define B_STAGE  36864              // hi 18432 + lo 18432
#define SM_TOTAL (B_BASE + 2 * B_STAGE)   // 110592 -> 2 CTAs/SM

__device__ __forceinline__ void load_B(
    int c, uint32_t stg, const bf16* whi, const bf16* wlo, int tid)
{
    const int r = tid >> 1;          // 0..127 (n)
    const int half = (tid & 1) * 32; // k offset within chunk
    const bf16* srcH = whi + ((size_t)c * 128 + r) * LDT + half;
    const bf16* srcL = wlo + ((size_t)c * 128 + r) * LDT + half;
    uint32_t dH = stg + r * (LDT * 2) + half * 2;
    uint32_t dL = stg + 18432 + r * (LDT * 2) + half * 2;
#pragma unroll
    for (int i = 0; i < 4; ++i) {
        cp16(dH + i * 16, srcH + i * 8);
        cp16(dL + i * 16, srcL + i * 8);
    }
}

__global__ void __launch_bounds__(256)
sage_wmma_kernel(
    const float* __restrict__ agg,
    const float* __restrict__ h,
    const bf16*  __restrict__ whi,   // layer base, chunk-tiled
    const bf16*  __restrict__ wlo,
    const float* __restrict__ bias,
    float*       __restrict__ out,   // padded to N_PAD rows
    int do_relu)
{
    extern __shared__ char smem[];
    const uint32_t sbase = smem_u32(smem);
    bf16* sAhi = reinterpret_cast<bf16*>(smem + A_HI_OFF);
    bf16* sAlo = reinterpret_cast<bf16*>(smem + A_LO_OFF);

    const int tid = threadIdx.x;
    const int wid = tid >> 5;
    const int block_row = blockIdx.x * 128;

    const int row  = tid >> 1;
    const int c0   = (tid & 1) * 32;
    const bool aok = (block_row + row) < N_NODES;

    const int wm = (wid & 1) * 64;
    const int wn = (wid >> 1) * 32;

    wmma::fragment<wmma::accumulator, 16, 16, 16, float> acc[4][2];
#pragma unroll
    for (int i = 0; i < 4; ++i)
#pragma unroll
        for (int j = 0; j < 2; ++j) wmma::fill_fragment(acc[i][j], 0.f);

    load_B(0, sbase + B_BASE,           whi, wlo, tid);
    CP_COMMIT();
    load_B(1, sbase + B_BASE + B_STAGE, whi, wlo, tid);
    CP_COMMIT();

    float4 av[8];
    {
        const float* ap = agg + (size_t)(block_row + row) * 128 + c0;
#pragma unroll
        for (int j = 0; j < 8; ++j)
            av[j] = aok ? __ldg(reinterpret_cast<const float4*>(ap) + j)
                        : make_float4(0.f, 0.f, 0.f, 0.f);
    }

#pragma unroll 1
    for (int c = 0; c < 4; ++c) {
#pragma unroll
        for (int j = 0; j < 8; ++j) {
            int eoff = row * LDT + c0 + j * 4;
            uint2 hi, lo;
            split4(av[j], hi, lo);
            *reinterpret_cast<uint2*>(sAhi + eoff) = hi;
            *reinterpret_cast<uint2*>(sAlo + eoff) = lo;
        }
        if (c < 3) CP_WAIT1(); else CP_WAIT0();
        __syncthreads();

        if (c < 3) {
            const int nc = c + 1;
            const float* Asrc = (nc < 2) ? agg : h;
            const int k0 = (nc & 1) * 64;
            const float* ap = Asrc + (size_t)(block_row + row) * 128 + k0 + c0;
#pragma unroll
            for (int j = 0; j < 8; ++j)
                av[j] = aok ? __ldg(reinterpret_cast<const float4*>(ap) + j)
                            : make_float4(0.f, 0.f, 0.f, 0.f);
        }

        const char* st = smem + B_BASE + (c & 1) * B_STAGE;
        const bf16* sBhi = reinterpret_cast<const bf16*>(st);
        const bf16* sBlo = reinterpret_cast<const bf16*>(st + 18432);

#pragma unroll
        for (int ks = 0; ks < 4; ++ks) {
            wmma::fragment<wmma::matrix_a, 16, 16, 16, bf16, wmma::row_major> fah[4], fal[4];
#pragma unroll
            for (int i = 0; i < 4; ++i) {
                wmma::load_matrix_sync(fah[i], sAhi + (wm + i * 16) * LDT + ks * 16, LDT);
                wmma::load_matrix_sync(fal[i], sAlo + (wm + i * 16) * LDT + ks * 16, LDT);
            }
#pragma unroll
            for (int j = 0; j < 2; ++j) {
                wmma::fragment<wmma::matrix_b, 16, 16, 16, bf16, wmma::col_major> fbh, fbl;
                wmma::load_matrix_sync(fbh, sBhi + (wn + j * 16) * LDT + ks * 16, LDT);
                wmma::load_matrix_sync(fbl, sBlo + (wn + j * 16) * LDT + ks * 16, LDT);
#pragma unroll
                for (int i = 0; i < 4; ++i) {
                    wmma::mma_sync(acc[i][j], fah[i], fbh, acc[i][j]);
                    wmma::mma_sync(acc[i][j], fah[i], fbl, acc[i][j]);
                    wmma::mma_sync(acc[i][j], fal[i], fbh, acc[i][j]);
                }
            }
        }
        __syncthreads();
        if (c + 2 < 4) {
            load_B(c + 2, sbase + B_BASE + (c & 1) * B_STAGE, whi, wlo, tid);
            CP_COMMIT();
        }
    }

    // ---- epilogue ----
    float* sBias = reinterpret_cast<float*>(smem);
    for (int idx = tid; idx < 16 * 128; idx += 256)
        sBias[idx] = __ldg(bias + (idx & 127));
    __syncthreads();

#pragma unroll
    for (int j = 0; j < 2; ++j) {
        wmma::fragment<wmma::accumulator, 16, 16, 16, float> bf;
        wmma::load_matrix_sync(bf, sBias + wn + j * 16, 128, wmma::mem_row_major);
#pragma unroll
        for (int i = 0; i < 4; ++i) {
#pragma unroll
            for (int e = 0; e < acc[i][j].num_elements; ++e) {
                float v = acc[i][j].x[e] + bf.x[e];
                acc[i][j].x[e] = do_relu ? fmaxf(v, 0.f) : v;
            }
            float* op = out + (size_t)(block_row + wm + i * 16) * 128 + wn + j * 16;
            wmma::store_matrix_sync(op, acc[i][j], 128, wmma::mem_row_major);
        }
    }
}

// ---------------- pooling ----------------
__global__ void __launch_bounds__(256) pool_kernel(
    const float* __restrict__ h,
    const int*   __restrict__ batch,
    float*       __restrict__ pooled)
{
    int node = (blockIdx.x * blockDim.x + threadIdx.x) >> 5;
    int lane = threadIdx.x & 31;
    if (node >= N_NODES) return;
    int g = __ldg(batch + node);
    float4 v = __ldg(reinterpret_cast<const float4*>(h + (size_t)node * 128) + lane);
    float* ap = pooled + (size_t)g * HIDDEN + lane * 4;
    asm volatile("red.global.add.v4.f32 [%0], {%1,%2,%3,%4};"
                 :: "l"(ap), "f"(v.x), "f"(v.y), "f"(v.z), "f"(v.w) : "memory");
}

// ---------------- output head ----------------
__global__ void out_kernel(
    const float* __restrict__ pooled,
    const float* __restrict__ Wout,
    const float* __restrict__ bout,
    float*       __restrict__ out)
{
    int idx = blockIdx.x * blockDim.x + threadIdx.x;
    if (idx >= NUM_GRAPHS * N_CLASSES) return;
    int g = idx / N_CLASSES;
    int c = idx % N_CLASSES;
    float s = __ldg(bout + c);
    const float* p = pooled + (size_t)g * HIDDEN;
    const float* w = Wout + (size_t)c * HIDDEN;
#pragma unroll 8
    for (int k = 0; k < HIDDEN; ++k) s = fmaf(p[k], w[k], s);
    out[idx] = s;
}

// ---------------- launch ----------------
extern "C" void kernel_launch(void* const* d_in, const int* in_sizes, int n_in,
                              void* d_out, int out_size)
{
    const float* x     = (const float*)d_in[0];
    const int*   ei    = (const int*)  d_in[1];
    const int*   batch = (const int*)  d_in[2];
    const float* W1l = (const float*)d_in[3];
    const float* b1  = (const float*)d_in[4];
    const float* W1r = (const float*)d_in[5];
    const float* W2l = (const float*)d_in[6];
    const float* b2  = (const float*)d_in[7];
    const float* W2r = (const float*)d_in[8];
    const float* W3l = (const float*)d_in[9];
    const float* b3  = (const float*)d_in[10];
    const float* W3r = (const float*)d_in[11];
    const float* Wout = (const float*)d_in[12];
    const float* bout = (const float*)d_in[13];
    float* out = (float*)d_out;

    float *agg, *h1, *h2, *pooled;
    bf16 *whi, *wlo;
    int *deg, *off, *cur, *srcs, *blksum, *blkoff;
    cudaGetSymbolAddress((void**)&agg,    g_agg);
    cudaGetSymbolAddress((void**)&h1,     g_h1);
    cudaGetSymbolAddress((void**)&h2,     g_h2);
    cudaGetSymbolAddress((void**)&whi,    g_whi);
    cudaGetSymbolAddress((void**)&wlo,    g_wlo);
    cudaGetSymbolAddress((void**)&pooled, g_pooled);
    cudaGetSymbolAddress((void**)&deg,    g_deg);
    cudaGetSymbolAddress((void**)&off,    g_off);
    cudaGetSymbolAddress((void**)&cur,    g_cur);
    cudaGetSymbolAddress((void**)&srcs,   g_srcs);
    cudaGetSymbolAddress((void**)&blksum, g_blksum);
    cudaGetSymbolAddress((void**)&blkoff, g_blkoff);

    cudaFuncSetAttribute(sage_wmma_kernel,
                         cudaFuncAttributeMaxDynamicSharedMemorySize, SM_TOTAL);

    const int edge_blocks = (N_EDGES + 255) / 256;
    const int node_blocks = NBLK;
    const int gemm_blocks = N_PAD / 128;   // 782
    const int warp_blocks = (N_NODES * 32 + 255) / 256;
    const int WSTRIDE = 4 * 128 * LDT;     // per-layer weight stride

    // one-time weight conversion
    cvt_w_kernel<<<(3 * 128 * 64 + 255) / 256, 256>>>(W1l, W1r, W2l, W2r, W3l, W3r, whi, wlo);

    // CSR build (multi-block scan)
    zero_deg_kernel<<<node_blocks, 256>>>(deg);
    hist_kernel<<<edge_blocks, 256>>>(ei, deg);
    partial_kernel<<<node_blocks, 256>>>(deg, blksum);
    scan_blocks_kernel<<<1, 512>>>(blksum, blkoff);
    fill_off_kernel<<<node_blocks, 256>>>(deg, blkoff, off, cur);
    fill_kernel<<<edge_blocks, 256>>>(ei, cur, srcs);

    // layer 1: x -> h1
    aggregate_kernel<<<warp_blocks, 256>>>(x, off, srcs, agg);
    sage_wmma_kernel<<<gemm_blocks, 256, SM_TOTAL>>>(agg, x, whi, wlo, b1, h1, 1);

    // layer 2: h1 -> h2
    aggregate_kernel<<<warp_blocks, 256>>>(h1, off, srcs, agg);
    sage_wmma_kernel<<<gemm_blocks, 256, SM_TOTAL>>>(agg, h1, whi + WSTRIDE, wlo + WSTRIDE, b2, h2, 1);

    // layer 3: h2 -> h1 (no relu)
    aggregate_kernel<<<warp_blocks, 256>>>(h2, off, srcs, agg);
    sage_wmma_kernel<<<gemm_blocks, 256, SM_TOTAL>>>(agg, h2, whi + 2 * WSTRIDE, wlo + 2 * WSTRIDE, b3, h1, 0);

    // pool + head
    cudaMemsetAsync(pooled, 0, NUM_GRAPHS * HIDDEN * sizeof(float));
    pool_kernel<<<warp_blocks, 256>>>(h1, batch, pooled);
    out_kernel<<<(NUM_GRAPHS * N_CLASSES + 127) / 128, 128>>>(pooled, Wout, bout, out);
}